// round 12
// baseline (speedup 1.0000x reference)
#include <cuda_runtime.h>
#include <math.h>

#define NIMG 24   // b*s = 4*6
#define NTASK 144 // b*s*s

// ---------------- device scratch (no allocations allowed) ----------------
__device__ float g_x [NIMG*3*64*64];
__device__ float g_f1[NIMG*32*32*32];
__device__ float g_f2[NIMG*48*16*16];
__device__ float g_f3[NIMG*64*64];    // [n][c][p], p = y*8+x
__device__ float g_u [NIMG*128*64];   // [n][k][p]  (transposed for smem loads)
__device__ float g_v [NIMG*64*128];   // [n][q][k]  (includes +bg1)
__device__ float g_P [NTASK];         // score[b][J][I]

// ---------------- packed f32x2 helpers (Blackwell FFMA2) ----------------
typedef unsigned long long u64t;
__device__ __forceinline__ u64t pack2(float lo, float hi) {
    u64t r; asm("mov.b64 %0, {%1, %2};" : "=l"(r) : "f"(lo), "f"(hi)); return r;
}
__device__ __forceinline__ void unpack2(u64t v, float& lo, float& hi) {
    asm("mov.b64 {%0, %1}, %2;" : "=f"(lo), "=f"(hi) : "l"(v));
}
__device__ __forceinline__ void fma2(u64t& d, u64t a, u64t b) {
    asm("fma.rn.f32x2 %0, %1, %2, %0;" : "+l"(d) : "l"(a), "l"(b));
}

// ---------------- pack support_x / query_x into g_x ----------------
__global__ void pack_kernel(const float* __restrict__ sx, const float* __restrict__ qx) {
    int idx = blockIdx.x * blockDim.x + threadIdx.x;
    if (idx >= NIMG * 12288) return;
    int n = idx / 12288, r = idx - n * 12288;
    int b = n / 6, s = n - b * 6;
    g_x[idx] = (s < 5) ? sx[(b * 5 + s) * 12288 + r] : qx[b * 12288 + r];
}

// ---------------- generic stride-2 SAME 3x3 conv + relu (conv1/conv2) ----------------
template<int CI, int HIN>
__device__ __forceinline__ void conv_body(const float* __restrict__ in,
                                          const float* __restrict__ wt,
                                          const float* __restrict__ bias,
                                          float* __restrict__ out, int CO) {
    constexpr int WIN = HIN, HOUT = HIN / 2, WOUT = HIN / 2;
    constexpr int PH = HIN + 1, PW = WIN + 1;
    constexpr int KK = CI * 9;
    constexpr int IN_ELEMS = CI * PH * PW;
    constexpr int WOFF = (IN_ELEMS + 3) & ~3;
    extern __shared__ float sm[];
    float* in_s = sm;
    float* w_s  = sm + WOFF;   // [KK][8]

    int n = blockIdx.x;
    int co0 = blockIdx.y * 8;
    int tid = threadIdx.x;

    for (int idx = tid; idx < IN_ELEMS; idx += blockDim.x) {
        int ci = idx / (PH * PW);
        int r = idx - ci * (PH * PW);
        int y = r / PW, x = r - y * PW;
        float v = 0.f;
        if (y < HIN && x < WIN) v = in[((n * CI + ci) * HIN + y) * WIN + x];
        in_s[idx] = v;
    }
    for (int idx = tid; idx < KK * 8; idx += blockDim.x) {
        int k = idx >> 3, c8 = idx & 7;
        w_s[idx] = wt[(co0 + c8) * KK + k];
    }
    __syncthreads();

    float bv[8];
    #pragma unroll
    for (int c8 = 0; c8 < 8; c8++) bv[c8] = bias[co0 + c8];

    for (int pos = tid; pos < HOUT * WOUT; pos += blockDim.x) {
        int y = pos / WOUT, x = pos - y * WOUT;
        float acc[8];
        #pragma unroll
        for (int c8 = 0; c8 < 8; c8++) acc[c8] = bv[c8];
        for (int ci = 0; ci < CI; ci++) {
            const float* ip = in_s + (ci * PH + 2 * y) * PW + 2 * x;
            #pragma unroll
            for (int kh = 0; kh < 3; kh++) {
                #pragma unroll
                for (int kw = 0; kw < 3; kw++) {
                    float iv = ip[kh * PW + kw];
                    int k = ci * 9 + kh * 3 + kw;
                    const float4 w0 = *(const float4*)(w_s + k * 8);
                    const float4 w1 = *(const float4*)(w_s + k * 8 + 4);
                    acc[0] = fmaf(iv, w0.x, acc[0]);
                    acc[1] = fmaf(iv, w0.y, acc[1]);
                    acc[2] = fmaf(iv, w0.z, acc[2]);
                    acc[3] = fmaf(iv, w0.w, acc[3]);
                    acc[4] = fmaf(iv, w1.x, acc[4]);
                    acc[5] = fmaf(iv, w1.y, acc[5]);
                    acc[6] = fmaf(iv, w1.z, acc[6]);
                    acc[7] = fmaf(iv, w1.w, acc[7]);
                }
            }
        }
        #pragma unroll
        for (int c8 = 0; c8 < 8; c8++)
            out[((n * CO + co0 + c8) * HOUT + y) * WOUT + x] = fmaxf(acc[c8], 0.f);
    }
}

__global__ void conv1_k(const float* wt, const float* b) { conv_body<3, 64>(g_x,  wt, b, g_f1, 32); }
__global__ void conv2_k(const float* wt, const float* b) { conv_body<32, 32>(g_f1, wt, b, g_f2, 48); }

// ---------------- conv3: 64 positions x 4 co-groups => all 256 threads active ----------------
// CI=48, HIN=16, grid (24, 2): co0 = blockIdx.y*32, threads: pos = tid&63, cog = tid>>6
__global__ void conv3_k(const float* __restrict__ wt, const float* __restrict__ bias) {
    constexpr int CI = 48, PH = 17, PW = 17, KK = CI * 9;           // 432
    constexpr int IN_ELEMS = CI * PH * PW;                          // 13872
    extern __shared__ float sm[];
    float* in_s = sm;
    float* w_s  = sm + IN_ELEMS;    // [4][KK][8] = 13824

    int n = blockIdx.x;
    int co0 = blockIdx.y * 32;
    int tid = threadIdx.x;

    for (int idx = tid; idx < IN_ELEMS; idx += 256) {
        int ci = idx / (PH * PW);
        int r = idx - ci * (PH * PW);
        int y = r / PW, x = r - y * PW;
        float v = 0.f;
        if (y < 16 && x < 16) v = g_f2[((n * CI + ci) * 16 + y) * 16 + x];
        in_s[idx] = v;
    }
    for (int idx = tid; idx < KK * 32; idx += 256) {
        int cog = idx / (KK * 8);
        int r = idx - cog * (KK * 8);
        int k = r >> 3, c8 = r & 7;
        w_s[idx] = wt[(co0 + cog * 8 + c8) * KK + k];
    }
    __syncthreads();

    int pos = tid & 63, cog = tid >> 6;
    int y = pos >> 3, x = pos & 7;
    const float* wg = w_s + cog * KK * 8;

    float acc[8];
    #pragma unroll
    for (int c8 = 0; c8 < 8; c8++) acc[c8] = bias[co0 + cog * 8 + c8];

    for (int ci = 0; ci < CI; ci++) {
        const float* ip = in_s + (ci * PH + 2 * y) * PW + 2 * x;
        #pragma unroll
        for (int kh = 0; kh < 3; kh++) {
            #pragma unroll
            for (int kw = 0; kw < 3; kw++) {
                float iv = ip[kh * PW + kw];
                int k = ci * 9 + kh * 3 + kw;
                const float4 w0 = *(const float4*)(wg + k * 8);
                const float4 w1 = *(const float4*)(wg + k * 8 + 4);
                acc[0] = fmaf(iv, w0.x, acc[0]);
                acc[1] = fmaf(iv, w0.y, acc[1]);
                acc[2] = fmaf(iv, w0.z, acc[2]);
                acc[3] = fmaf(iv, w0.w, acc[3]);
                acc[4] = fmaf(iv, w1.x, acc[4]);
                acc[5] = fmaf(iv, w1.y, acc[5]);
                acc[6] = fmaf(iv, w1.z, acc[6]);
                acc[7] = fmaf(iv, w1.w, acc[7]);
            }
        }
    }
    #pragma unroll
    for (int c8 = 0; c8 < 8; c8++)
        g_f3[((n * 64 + co0 + cog * 8 + c8) * 8 + y) * 8 + x] = fmaxf(acc[c8], 0.f);
}

// ---------------- logits + cls_loss (single CTA) ----------------
__global__ void logits_kernel(const float* __restrict__ Wlog, const float* __restrict__ blog,
                              const int* __restrict__ sy, const int* __restrict__ qy,
                              float* __restrict__ out) {
    __shared__ float pooled[NIMG * 64];
    __shared__ float lg[NIMG * 64];
    __shared__ float lps[NIMG];
    int tid = threadIdx.x;
    for (int idx = tid; idx < NIMG * 64; idx += 256) {
        const float* f = g_f3 + idx * 64;
        float s = 0.f;
        #pragma unroll 4
        for (int p = 0; p < 64; p++) s += f[p];
        pooled[idx] = s * (1.f / 64.f);
    }
    __syncthreads();
    for (int idx = tid; idx < NIMG * 64; idx += 256) {
        int n = idx >> 6, cl = idx & 63;
        const float* pn = pooled + n * 64;
        float s = blog[cl];
        for (int c = 0; c < 64; c++) s = fmaf(pn[c], Wlog[c * 64 + cl], s);
        lg[idx] = s;
    }
    __syncthreads();
    if (tid < NIMG) {
        int n = tid, b = n / 6, ss = n - b * 6;
        int lab = (ss < 5) ? sy[b * 5 + ss] : qy[b];
        const float* l = lg + n * 64;
        float m = l[0];
        for (int c = 1; c < 64; c++) m = fmaxf(m, l[c]);
        float se = 0.f;
        for (int c = 0; c < 64; c++) se += expf(l[c] - m);
        lps[n] = l[lab] - m - logf(se);
    }
    __syncthreads();
    if (tid == 0) {
        float s = 0.f;
        for (int n = 0; n < NIMG; n++) s += lps[n];
        out[0] = -s / (float)NIMG;
    }
}

// ---------------- u = a@W1a, v = a@W1b + bg1 ----------------
__global__ void uv_kernel(const float* __restrict__ Wg1, const float* __restrict__ bg1) {
    extern __shared__ float sm[];
    float* a_s  = sm;                 // [64][68]
    float* wa_s = sm + 64 * 68;       // [66][64]
    float* wb_s = wa_s + 66 * 64;     // [66][64]
    float* bgs  = wb_s + 66 * 64;     // [64]
    int n = blockIdx.x;
    int k0 = blockIdx.y * 64;
    int tid = threadIdx.x;

    for (int idx = tid; idx < 64 * 64; idx += 256) {
        int c = idx >> 6, p = idx & 63;
        a_s[p * 68 + c] = g_f3[(n * 64 + c) * 64 + p];
    }
    for (int idx = tid; idx < 66 * 64; idx += 256) {
        int c = idx >> 6, kk = idx & 63;
        wa_s[idx] = Wg1[c * 128 + k0 + kk];
        wb_s[idx] = Wg1[(66 + c) * 128 + k0 + kk];
    }
    if (tid < 64) {
        bgs[tid] = bg1[k0 + tid];
        int p = tid;
        a_s[p * 68 + 64] = (float)(p >> 3) * 0.125f;
        a_s[p * 68 + 65] = (float)(p & 7) * 0.125f;
    }
    __syncthreads();

    int kg = tid & 7, pgg = tid >> 3;
    int p0 = pgg * 2, kb = kg * 8;
    float ua[2][8], va[2][8];
    #pragma unroll
    for (int kk = 0; kk < 8; kk++) {
        ua[0][kk] = 0.f; ua[1][kk] = 0.f;
        va[0][kk] = bgs[kb + kk]; va[1][kk] = bgs[kb + kk];
    }
    for (int c = 0; c < 66; c++) {
        float a0 = a_s[p0 * 68 + c];
        float a1 = a_s[(p0 + 1) * 68 + c];
        float4 w0 = *(const float4*)(wa_s + c * 64 + kb);
        float4 w1 = *(const float4*)(wa_s + c * 64 + kb + 4);
        float4 x0 = *(const float4*)(wb_s + c * 64 + kb);
        float4 x1 = *(const float4*)(wb_s + c * 64 + kb + 4);
        float wv[8] = {w0.x, w0.y, w0.z, w0.w, w1.x, w1.y, w1.z, w1.w};
        float xv[8] = {x0.x, x0.y, x0.z, x0.w, x1.x, x1.y, x1.z, x1.w};
        #pragma unroll
        for (int kk = 0; kk < 8; kk++) {
            ua[0][kk] = fmaf(a0, wv[kk], ua[0][kk]);
            ua[1][kk] = fmaf(a1, wv[kk], ua[1][kk]);
            va[0][kk] = fmaf(a0, xv[kk], va[0][kk]);
            va[1][kk] = fmaf(a1, xv[kk], va[1][kk]);
        }
    }
    #pragma unroll
    for (int tp = 0; tp < 2; tp++)
        #pragma unroll
        for (int kk = 0; kk < 8; kk++) {
            int gk = k0 + kb + kk;
            g_u[(n * 128 + gk) * 64 + p0 + tp] = ua[tp][kk];
            g_v[(n * 64 + p0 + tp) * 128 + gk] = va[tp][kk];
        }
}

// ---------------- relation network core (FFMA2 packed): one CTA per (b,J,I) ----------------
__global__ void __launch_bounds__(256, 1)
relnet_kernel(const float* __restrict__ Wg2, const float* __restrict__ bg2,
              const float* __restrict__ Wf1, const float* __restrict__ bf1,
              const float* __restrict__ Wf2, const float* __restrict__ bf2) {
    extern __shared__ float sm[];
    float* Us   = sm;            // [128][64]  u[ni][k][p]
    float* Vs   = sm + 8192;     // [64][128]  v[nj][q][k]
    float* Ws   = sm + 16384;    // [128][64]  Wg2[k][c]
    float* part = sm + 24576;    // [32][64]
    float* xf   = sm + 26624;    // [64]
    float* hsm  = sm + 26688;    // [16]

    int task = blockIdx.x;
    int b = task / 36, rem = task - b * 36;
    int J = rem / 6, I = rem - J * 6;
    int ni = b * 6 + I, nj = b * 6 + J;
    int tid = threadIdx.x;

    for (int idx = tid; idx < 8192; idx += 256) {
        Us[idx] = g_u[ni * 8192 + idx];
        Vs[idx] = g_v[nj * 8192 + idx];
        Ws[idx] = Wg2[idx];
    }
    __syncthreads();

    int cg = tid & 7, pg = tid >> 3;
    int c0 = cg << 3;
    float bgr[8];
    #pragma unroll
    for (int t = 0; t < 8; t++) bgr[t] = bg2[c0 + t];

    float acc8[8] = {0.f, 0.f, 0.f, 0.f, 0.f, 0.f, 0.f, 0.f};

    for (int it = 0; it < 16; ++it) {
        int pt = pg + (it << 5);
        int q = pt >> 3;
        int p0 = (pt & 7) << 3;
        const float* vq = Vs + q * 128;
        const float* up = Us + p0;
        const float* wp = Ws + c0;

        u64t ct2[8][4];
        #pragma unroll
        for (int tp = 0; tp < 8; tp++)
            #pragma unroll
            for (int j = 0; j < 4; j++) ct2[tp][j] = 0ULL;

        #pragma unroll 2
        for (int k = 0; k < 128; ++k) {
            const float* uk = up + k * 64;
            float4 uA = *(const float4*)uk;
            float4 uB = *(const float4*)(uk + 4);
            // weight pairs along tc: contiguous floats -> 64-bit packed loads
            ulonglong2 wA = *(const ulonglong2*)(wp + k * 64);
            ulonglong2 wB = *(const ulonglong2*)(wp + k * 64 + 4);
            float vk = vq[k];

            float h0 = fmaxf(uA.x + vk, 0.f);
            float h1 = fmaxf(uA.y + vk, 0.f);
            float h2 = fmaxf(uA.z + vk, 0.f);
            float h3 = fmaxf(uA.w + vk, 0.f);
            float h4 = fmaxf(uB.x + vk, 0.f);
            float h5 = fmaxf(uB.y + vk, 0.f);
            float h6 = fmaxf(uB.z + vk, 0.f);
            float h7 = fmaxf(uB.w + vk, 0.f);
            u64t hh[8];
            hh[0] = pack2(h0, h0); hh[1] = pack2(h1, h1);
            hh[2] = pack2(h2, h2); hh[3] = pack2(h3, h3);
            hh[4] = pack2(h4, h4); hh[5] = pack2(h5, h5);
            hh[6] = pack2(h6, h6); hh[7] = pack2(h7, h7);
            u64t w2v[4] = {wA.x, wA.y, wB.x, wB.y};

            #pragma unroll
            for (int tp = 0; tp < 8; tp++) {
                fma2(ct2[tp][0], hh[tp], w2v[0]);
                fma2(ct2[tp][1], hh[tp], w2v[1]);
                fma2(ct2[tp][2], hh[tp], w2v[2]);
                fma2(ct2[tp][3], hh[tp], w2v[3]);
            }
        }

        #pragma unroll
        for (int tp = 0; tp < 8; tp++) {
            #pragma unroll
            for (int j = 0; j < 4; j++) {
                float lo, hi;
                unpack2(ct2[tp][j], lo, hi);
                acc8[2 * j]     += fmaxf(lo + bgr[2 * j],     0.f);
                acc8[2 * j + 1] += fmaxf(hi + bgr[2 * j + 1], 0.f);
            }
        }
    }

    #pragma unroll
    for (int t = 0; t < 8; t++) part[pg * 64 + c0 + t] = acc8[t];
    __syncthreads();

    if (tid < 64) {
        float s = 0.f;
        for (int g = 0; g < 32; g++) s += part[g * 64 + tid];
        xf[tid] = s;
    }
    __syncthreads();
    if (tid < 16) {
        float s = bf1[tid];
        for (int c = 0; c < 64; c++) s = fmaf(xf[c], Wf1[c * 16 + tid], s);
        hsm[tid] = fmaxf(s, 0.f);
    }
    __syncthreads();
    if (tid == 0) {
        float s = bf2[0];
        for (int t = 0; t < 16; t++) s = fmaf(hsm[t], Wf2[t], s);
        g_P[task] = 1.f / (1.f + expf(-s));
    }
}

// ---------------- final losses ----------------
__global__ void loss_kernel(const int* __restrict__ sy, const int* __restrict__ qy,
                            float* __restrict__ out) {
    __shared__ float es[256];
    __shared__ float s2[4], a2[4];
    int tid = threadIdx.x;
    if (tid < 4) { s2[tid] = 0.f; a2[tid] = 0.f; }
    __syncthreads();
    float e = 0.f;
    if (tid < NTASK) {
        int b = tid / 36, r = tid - b * 36;
        int J = r / 6, I = r - J * 6;
        float p  = g_P[tid];
        float pt = g_P[b * 36 + I * 6 + J];
        int labJ = (J < 5) ? sy[b * 5 + J] : qy[b];
        int labI = (I < 5) ? sy[b * 5 + I] : qy[b];
        float y = (labJ == labI) ? 1.f : 0.f;
        e = (p - y) * (p - y);
        float symv = 0.5f * (p + pt), antiv = 0.5f * (p - pt);
        atomicAdd(&s2[b], symv * symv);
        atomicAdd(&a2[b], antiv * antiv);
    }
    es[tid] = e;
    __syncthreads();
    for (int off = 128; off > 0; off >>= 1) {
        if (tid < off) es[tid] += es[tid + off];
        __syncthreads();
    }
    if (tid == 0) {
        float euc = es[0] / (float)NTASK;
        float sl = 0.f;
        for (int bb = 0; bb < 4; bb++) {
            float sn = sqrtf(s2[bb]), an = sqrtf(a2[bb]);
            sl += (sn - an) / (sn + an);
        }
        sl *= 0.25f;
        out[2] = sl;
        out[1] = euc - 0.1f * sl;
    }
}

// ---------------- launch ----------------
extern "C" void kernel_launch(void* const* d_in, const int* in_sizes, int n_in,
                              void* d_out, int out_size) {
    const float* sx   = (const float*)d_in[0];
    const int*   sy   = (const int*)  d_in[1];
    const float* qx   = (const float*)d_in[2];
    const int*   qy   = (const int*)  d_in[3];
    const float* k1   = (const float*)d_in[4];
    const float* bc1  = (const float*)d_in[5];
    const float* k2   = (const float*)d_in[6];
    const float* bc2  = (const float*)d_in[7];
    const float* k3   = (const float*)d_in[8];
    const float* bc3  = (const float*)d_in[9];
    const float* Wlog = (const float*)d_in[10];
    const float* blog = (const float*)d_in[11];
    const float* Wg1  = (const float*)d_in[12];
    const float* bg1  = (const float*)d_in[13];
    const float* Wg2  = (const float*)d_in[14];
    const float* bg2  = (const float*)d_in[15];
    const float* Wf1  = (const float*)d_in[16];
    const float* bf1  = (const float*)d_in[17];
    const float* Wf2  = (const float*)d_in[18];
    const float* bf2  = (const float*)d_in[19];
    float* out = (float*)d_out;

    // dynamic smem sizes (bytes)
    const int smem_c1  = (((3  * 65 * 65 + 3) & ~3) + 8 * 27 ) * 4;   //  ~51.6 KB
    const int smem_c2  = (((32 * 33 * 33 + 3) & ~3) + 8 * 288) * 4;   // ~148.6 KB
    const int smem_c3  = (48 * 17 * 17 + 48 * 9 * 32) * 4;            // ~110.8 KB
    const int smem_uv  = (64 * 68 + 2 * 66 * 64 + 64) * 4;            //  ~51.5 KB
    const int smem_rel = (3 * 8192 + 2048 + 64 + 16) * 4;             // ~106.8 KB

    cudaFuncSetAttribute(conv1_k,       cudaFuncAttributeMaxDynamicSharedMemorySize, smem_c1);
    cudaFuncSetAttribute(conv2_k,       cudaFuncAttributeMaxDynamicSharedMemorySize, smem_c2);
    cudaFuncSetAttribute(conv3_k,       cudaFuncAttributeMaxDynamicSharedMemorySize, smem_c3);
    cudaFuncSetAttribute(uv_kernel,     cudaFuncAttributeMaxDynamicSharedMemorySize, smem_uv);
    cudaFuncSetAttribute(relnet_kernel, cudaFuncAttributeMaxDynamicSharedMemorySize, smem_rel);

    pack_kernel<<<(NIMG * 12288 + 255) / 256, 256>>>(sx, qx);
    conv1_k<<<dim3(NIMG, 4), 256, smem_c1>>>(k1, bc1);
    conv2_k<<<dim3(NIMG, 6), 256, smem_c2>>>(k2, bc2);
    conv3_k<<<dim3(NIMG, 2), 256, smem_c3>>>(k3, bc3);
    logits_kernel<<<1, 256>>>(Wlog, blog, sy, qy, out);
    uv_kernel<<<dim3(NIMG, 2), 256, smem_uv>>>(Wg1, bg1);
    relnet_kernel<<<NTASK, 256, smem_rel>>>(Wg2, bg2, Wf1, bf1, Wf2, bf2);
    loss_kernel<<<1, 256>>>(sy, qy, out);
}

// round 13
// speedup vs baseline: 1.0004x; 1.0004x over previous
#include <cuda_runtime.h>
#include <math.h>

#define NIMG 24   // b*s = 4*6
#define NTASK 144 // b*s*s

// ---------------- device scratch (no allocations allowed) ----------------
__device__ float g_x [NIMG*3*64*64];
__device__ float g_f1[NIMG*32*32*32];
__device__ float g_f2[NIMG*48*16*16];
__device__ float g_f3[NIMG*64*64];    // [n][c][p], p = y*8+x
__device__ float g_u [NIMG*128*64];   // [n][k][p]  (transposed for smem loads)
__device__ float g_v [NIMG*64*128];   // [n][q][k]  (includes +bg1)
__device__ float g_P [NTASK];         // score[b][J][I]

// ---------------- packed f32x2 helpers (Blackwell FFMA2) ----------------
typedef unsigned long long u64t;
__device__ __forceinline__ u64t pack2(float lo, float hi) {
    u64t r; asm("mov.b64 %0, {%1, %2};" : "=l"(r) : "f"(lo), "f"(hi)); return r;
}
__device__ __forceinline__ void unpack2(u64t v, float& lo, float& hi) {
    asm("mov.b64 {%0, %1}, %2;" : "=f"(lo), "=f"(hi) : "l"(v));
}
__device__ __forceinline__ void fma2(u64t& d, u64t a, u64t b) {
    asm("fma.rn.f32x2 %0, %1, %2, %0;" : "+l"(d) : "l"(a), "l"(b));
}

// ---------------- pack support_x / query_x into g_x ----------------
__global__ void pack_kernel(const float* __restrict__ sx, const float* __restrict__ qx) {
    int idx = blockIdx.x * blockDim.x + threadIdx.x;
    if (idx >= NIMG * 12288) return;
    int n = idx / 12288, r = idx - n * 12288;
    int b = n / 6, s = n - b * 6;
    g_x[idx] = (s < 5) ? sx[(b * 5 + s) * 12288 + r] : qx[b * 12288 + r];
}

// ---------------- generic stride-2 SAME 3x3 conv + relu (conv1/conv2) ----------------
template<int CI, int HIN>
__device__ __forceinline__ void conv_body(const float* __restrict__ in,
                                          const float* __restrict__ wt,
                                          const float* __restrict__ bias,
                                          float* __restrict__ out, int CO) {
    constexpr int WIN = HIN, HOUT = HIN / 2, WOUT = HIN / 2;
    constexpr int PH = HIN + 1, PW = WIN + 1;
    constexpr int KK = CI * 9;
    constexpr int IN_ELEMS = CI * PH * PW;
    constexpr int WOFF = (IN_ELEMS + 3) & ~3;
    extern __shared__ float sm[];
    float* in_s = sm;
    float* w_s  = sm + WOFF;   // [KK][8]

    int n = blockIdx.x;
    int co0 = blockIdx.y * 8;
    int tid = threadIdx.x;

    for (int idx = tid; idx < IN_ELEMS; idx += blockDim.x) {
        int ci = idx / (PH * PW);
        int r = idx - ci * (PH * PW);
        int y = r / PW, x = r - y * PW;
        float v = 0.f;
        if (y < HIN && x < WIN) v = in[((n * CI + ci) * HIN + y) * WIN + x];
        in_s[idx] = v;
    }
    for (int idx = tid; idx < KK * 8; idx += blockDim.x) {
        int k = idx >> 3, c8 = idx & 7;
        w_s[idx] = wt[(co0 + c8) * KK + k];
    }
    __syncthreads();

    float bv[8];
    #pragma unroll
    for (int c8 = 0; c8 < 8; c8++) bv[c8] = bias[co0 + c8];

    for (int pos = tid; pos < HOUT * WOUT; pos += blockDim.x) {
        int y = pos / WOUT, x = pos - y * WOUT;
        float acc[8];
        #pragma unroll
        for (int c8 = 0; c8 < 8; c8++) acc[c8] = bv[c8];
        for (int ci = 0; ci < CI; ci++) {
            const float* ip = in_s + (ci * PH + 2 * y) * PW + 2 * x;
            #pragma unroll
            for (int kh = 0; kh < 3; kh++) {
                #pragma unroll
                for (int kw = 0; kw < 3; kw++) {
                    float iv = ip[kh * PW + kw];
                    int k = ci * 9 + kh * 3 + kw;
                    const float4 w0 = *(const float4*)(w_s + k * 8);
                    const float4 w1 = *(const float4*)(w_s + k * 8 + 4);
                    acc[0] = fmaf(iv, w0.x, acc[0]);
                    acc[1] = fmaf(iv, w0.y, acc[1]);
                    acc[2] = fmaf(iv, w0.z, acc[2]);
                    acc[3] = fmaf(iv, w0.w, acc[3]);
                    acc[4] = fmaf(iv, w1.x, acc[4]);
                    acc[5] = fmaf(iv, w1.y, acc[5]);
                    acc[6] = fmaf(iv, w1.z, acc[6]);
                    acc[7] = fmaf(iv, w1.w, acc[7]);
                }
            }
        }
        #pragma unroll
        for (int c8 = 0; c8 < 8; c8++)
            out[((n * CO + co0 + c8) * HOUT + y) * WOUT + x] = fmaxf(acc[c8], 0.f);
    }
}

__global__ void conv1_k(const float* wt, const float* b) { conv_body<3, 64>(g_x,  wt, b, g_f1, 32); }
__global__ void conv2_k(const float* wt, const float* b) { conv_body<32, 32>(g_f1, wt, b, g_f2, 48); }

// ---------------- conv3: 64 positions x 4 co-groups => all 256 threads active ----------------
// CI=48, HIN=16, grid (24, 2): co0 = blockIdx.y*32, threads: pos = tid&63, cog = tid>>6
__global__ void conv3_k(const float* __restrict__ wt, const float* __restrict__ bias) {
    constexpr int CI = 48, PH = 17, PW = 17, KK = CI * 9;           // 432
    constexpr int IN_ELEMS = CI * PH * PW;                          // 13872
    extern __shared__ float sm[];
    float* in_s = sm;
    float* w_s  = sm + IN_ELEMS;    // [4][KK][8] = 13824

    int n = blockIdx.x;
    int co0 = blockIdx.y * 32;
    int tid = threadIdx.x;

    for (int idx = tid; idx < IN_ELEMS; idx += 256) {
        int ci = idx / (PH * PW);
        int r = idx - ci * (PH * PW);
        int y = r / PW, x = r - y * PW;
        float v = 0.f;
        if (y < 16 && x < 16) v = g_f2[((n * CI + ci) * 16 + y) * 16 + x];
        in_s[idx] = v;
    }
    for (int idx = tid; idx < KK * 32; idx += 256) {
        int cog = idx / (KK * 8);
        int r = idx - cog * (KK * 8);
        int k = r >> 3, c8 = r & 7;
        w_s[idx] = wt[(co0 + cog * 8 + c8) * KK + k];
    }
    __syncthreads();

    int pos = tid & 63, cog = tid >> 6;
    int y = pos >> 3, x = pos & 7;
    const float* wg = w_s + cog * KK * 8;

    float acc[8];
    #pragma unroll
    for (int c8 = 0; c8 < 8; c8++) acc[c8] = bias[co0 + cog * 8 + c8];

    for (int ci = 0; ci < CI; ci++) {
        const float* ip = in_s + (ci * PH + 2 * y) * PW + 2 * x;
        #pragma unroll
        for (int kh = 0; kh < 3; kh++) {
            #pragma unroll
            for (int kw = 0; kw < 3; kw++) {
                float iv = ip[kh * PW + kw];
                int k = ci * 9 + kh * 3 + kw;
                const float4 w0 = *(const float4*)(wg + k * 8);
                const float4 w1 = *(const float4*)(wg + k * 8 + 4);
                acc[0] = fmaf(iv, w0.x, acc[0]);
                acc[1] = fmaf(iv, w0.y, acc[1]);
                acc[2] = fmaf(iv, w0.z, acc[2]);
                acc[3] = fmaf(iv, w0.w, acc[3]);
                acc[4] = fmaf(iv, w1.x, acc[4]);
                acc[5] = fmaf(iv, w1.y, acc[5]);
                acc[6] = fmaf(iv, w1.z, acc[6]);
                acc[7] = fmaf(iv, w1.w, acc[7]);
            }
        }
    }
    #pragma unroll
    for (int c8 = 0; c8 < 8; c8++)
        g_f3[((n * 64 + co0 + cog * 8 + c8) * 8 + y) * 8 + x] = fmaxf(acc[c8], 0.f);
}

// ---------------- logits + cls_loss (single CTA) ----------------
__global__ void logits_kernel(const float* __restrict__ Wlog, const float* __restrict__ blog,
                              const int* __restrict__ sy, const int* __restrict__ qy,
                              float* __restrict__ out) {
    __shared__ float pooled[NIMG * 64];
    __shared__ float lg[NIMG * 64];
    __shared__ float lps[NIMG];
    int tid = threadIdx.x;
    for (int idx = tid; idx < NIMG * 64; idx += 256) {
        const float* f = g_f3 + idx * 64;
        float s = 0.f;
        #pragma unroll 4
        for (int p = 0; p < 64; p++) s += f[p];
        pooled[idx] = s * (1.f / 64.f);
    }
    __syncthreads();
    for (int idx = tid; idx < NIMG * 64; idx += 256) {
        int n = idx >> 6, cl = idx & 63;
        const float* pn = pooled + n * 64;
        float s = blog[cl];
        for (int c = 0; c < 64; c++) s = fmaf(pn[c], Wlog[c * 64 + cl], s);
        lg[idx] = s;
    }
    __syncthreads();
    if (tid < NIMG) {
        int n = tid, b = n / 6, ss = n - b * 6;
        int lab = (ss < 5) ? sy[b * 5 + ss] : qy[b];
        const float* l = lg + n * 64;
        float m = l[0];
        for (int c = 1; c < 64; c++) m = fmaxf(m, l[c]);
        float se = 0.f;
        for (int c = 0; c < 64; c++) se += expf(l[c] - m);
        lps[n] = l[lab] - m - logf(se);
    }
    __syncthreads();
    if (tid == 0) {
        float s = 0.f;
        for (int n = 0; n < NIMG; n++) s += lps[n];
        out[0] = -s / (float)NIMG;
    }
}

// ---------------- u = a@W1a, v = a@W1b + bg1 ----------------
__global__ void uv_kernel(const float* __restrict__ Wg1, const float* __restrict__ bg1) {
    extern __shared__ float sm[];
    float* a_s  = sm;                 // [64][68]
    float* wa_s = sm + 64 * 68;       // [66][64]
    float* wb_s = wa_s + 66 * 64;     // [66][64]
    float* bgs  = wb_s + 66 * 64;     // [64]
    int n = blockIdx.x;
    int k0 = blockIdx.y * 64;
    int tid = threadIdx.x;

    for (int idx = tid; idx < 64 * 64; idx += 256) {
        int c = idx >> 6, p = idx & 63;
        a_s[p * 68 + c] = g_f3[(n * 64 + c) * 64 + p];
    }
    for (int idx = tid; idx < 66 * 64; idx += 256) {
        int c = idx >> 6, kk = idx & 63;
        wa_s[idx] = Wg1[c * 128 + k0 + kk];
        wb_s[idx] = Wg1[(66 + c) * 128 + k0 + kk];
    }
    if (tid < 64) {
        bgs[tid] = bg1[k0 + tid];
        int p = tid;
        a_s[p * 68 + 64] = (float)(p >> 3) * 0.125f;
        a_s[p * 68 + 65] = (float)(p & 7) * 0.125f;
    }
    __syncthreads();

    int kg = tid & 7, pgg = tid >> 3;
    int p0 = pgg * 2, kb = kg * 8;
    float ua[2][8], va[2][8];
    #pragma unroll
    for (int kk = 0; kk < 8; kk++) {
        ua[0][kk] = 0.f; ua[1][kk] = 0.f;
        va[0][kk] = bgs[kb + kk]; va[1][kk] = bgs[kb + kk];
    }
    for (int c = 0; c < 66; c++) {
        float a0 = a_s[p0 * 68 + c];
        float a1 = a_s[(p0 + 1) * 68 + c];
        float4 w0 = *(const float4*)(wa_s + c * 64 + kb);
        float4 w1 = *(const float4*)(wa_s + c * 64 + kb + 4);
        float4 x0 = *(const float4*)(wb_s + c * 64 + kb);
        float4 x1 = *(const float4*)(wb_s + c * 64 + kb + 4);
        float wv[8] = {w0.x, w0.y, w0.z, w0.w, w1.x, w1.y, w1.z, w1.w};
        float xv[8] = {x0.x, x0.y, x0.z, x0.w, x1.x, x1.y, x1.z, x1.w};
        #pragma unroll
        for (int kk = 0; kk < 8; kk++) {
            ua[0][kk] = fmaf(a0, wv[kk], ua[0][kk]);
            ua[1][kk] = fmaf(a1, wv[kk], ua[1][kk]);
            va[0][kk] = fmaf(a0, xv[kk], va[0][kk]);
            va[1][kk] = fmaf(a1, xv[kk], va[1][kk]);
        }
    }
    #pragma unroll
    for (int tp = 0; tp < 2; tp++)
        #pragma unroll
        for (int kk = 0; kk < 8; kk++) {
            int gk = k0 + kb + kk;
            g_u[(n * 128 + gk) * 64 + p0 + tp] = ua[tp][kk];
            g_v[(n * 64 + p0 + tp) * 128 + gk] = va[tp][kk];
        }
}

// ---------------- relation network core (FFMA2 packed): one CTA per (b,J,I) ----------------
__global__ void __launch_bounds__(256, 1)
relnet_kernel(const float* __restrict__ Wg2, const float* __restrict__ bg2,
              const float* __restrict__ Wf1, const float* __restrict__ bf1,
              const float* __restrict__ Wf2, const float* __restrict__ bf2) {
    extern __shared__ float sm[];
    float* Us   = sm;            // [128][64]  u[ni][k][p]
    float* Vs   = sm + 8192;     // [64][128]  v[nj][q][k]
    float* Ws   = sm + 16384;    // [128][64]  Wg2[k][c]
    float* part = sm + 24576;    // [32][64]
    float* xf   = sm + 26624;    // [64]
    float* hsm  = sm + 26688;    // [16]

    int task = blockIdx.x;
    int b = task / 36, rem = task - b * 36;
    int J = rem / 6, I = rem - J * 6;
    int ni = b * 6 + I, nj = b * 6 + J;
    int tid = threadIdx.x;

    for (int idx = tid; idx < 8192; idx += 256) {
        Us[idx] = g_u[ni * 8192 + idx];
        Vs[idx] = g_v[nj * 8192 + idx];
        Ws[idx] = Wg2[idx];
    }
    __syncthreads();

    int cg = tid & 7, pg = tid >> 3;
    int c0 = cg << 3;
    float bgr[8];
    #pragma unroll
    for (int t = 0; t < 8; t++) bgr[t] = bg2[c0 + t];

    float acc8[8] = {0.f, 0.f, 0.f, 0.f, 0.f, 0.f, 0.f, 0.f};

    for (int it = 0; it < 16; ++it) {
        int pt = pg + (it << 5);
        int q = pt >> 3;
        int p0 = (pt & 7) << 3;
        const float* vq = Vs + q * 128;
        const float* up = Us + p0;
        const float* wp = Ws + c0;

        u64t ct2[8][4];
        #pragma unroll
        for (int tp = 0; tp < 8; tp++)
            #pragma unroll
            for (int j = 0; j < 4; j++) ct2[tp][j] = 0ULL;

        #pragma unroll 2
        for (int k = 0; k < 128; ++k) {
            const float* uk = up + k * 64;
            float4 uA = *(const float4*)uk;
            float4 uB = *(const float4*)(uk + 4);
            // weight pairs along tc: contiguous floats -> 64-bit packed loads
            ulonglong2 wA = *(const ulonglong2*)(wp + k * 64);
            ulonglong2 wB = *(const ulonglong2*)(wp + k * 64 + 4);
            float vk = vq[k];

            float h0 = fmaxf(uA.x + vk, 0.f);
            float h1 = fmaxf(uA.y + vk, 0.f);
            float h2 = fmaxf(uA.z + vk, 0.f);
            float h3 = fmaxf(uA.w + vk, 0.f);
            float h4 = fmaxf(uB.x + vk, 0.f);
            float h5 = fmaxf(uB.y + vk, 0.f);
            float h6 = fmaxf(uB.z + vk, 0.f);
            float h7 = fmaxf(uB.w + vk, 0.f);
            u64t hh[8];
            hh[0] = pack2(h0, h0); hh[1] = pack2(h1, h1);
            hh[2] = pack2(h2, h2); hh[3] = pack2(h3, h3);
            hh[4] = pack2(h4, h4); hh[5] = pack2(h5, h5);
            hh[6] = pack2(h6, h6); hh[7] = pack2(h7, h7);
            u64t w2v[4] = {wA.x, wA.y, wB.x, wB.y};

            #pragma unroll
            for (int tp = 0; tp < 8; tp++) {
                fma2(ct2[tp][0], hh[tp], w2v[0]);
                fma2(ct2[tp][1], hh[tp], w2v[1]);
                fma2(ct2[tp][2], hh[tp], w2v[2]);
                fma2(ct2[tp][3], hh[tp], w2v[3]);
            }
        }

        #pragma unroll
        for (int tp = 0; tp < 8; tp++) {
            #pragma unroll
            for (int j = 0; j < 4; j++) {
                float lo, hi;
                unpack2(ct2[tp][j], lo, hi);
                acc8[2 * j]     += fmaxf(lo + bgr[2 * j],     0.f);
                acc8[2 * j + 1] += fmaxf(hi + bgr[2 * j + 1], 0.f);
            }
        }
    }

    #pragma unroll
    for (int t = 0; t < 8; t++) part[pg * 64 + c0 + t] = acc8[t];
    __syncthreads();

    if (tid < 64) {
        float s = 0.f;
        for (int g = 0; g < 32; g++) s += part[g * 64 + tid];
        xf[tid] = s;
    }
    __syncthreads();
    if (tid < 16) {
        float s = bf1[tid];
        for (int c = 0; c < 64; c++) s = fmaf(xf[c], Wf1[c * 16 + tid], s);
        hsm[tid] = fmaxf(s, 0.f);
    }
    __syncthreads();
    if (tid == 0) {
        float s = bf2[0];
        for (int t = 0; t < 16; t++) s = fmaf(hsm[t], Wf2[t], s);
        g_P[task] = 1.f / (1.f + expf(-s));
    }
}

// ---------------- final losses ----------------
__global__ void loss_kernel(const int* __restrict__ sy, const int* __restrict__ qy,
                            float* __restrict__ out) {
    __shared__ float es[256];
    __shared__ float s2[4], a2[4];
    int tid = threadIdx.x;
    if (tid < 4) { s2[tid] = 0.f; a2[tid] = 0.f; }
    __syncthreads();
    float e = 0.f;
    if (tid < NTASK) {
        int b = tid / 36, r = tid - b * 36;
        int J = r / 6, I = r - J * 6;
        float p  = g_P[tid];
        float pt = g_P[b * 36 + I * 6 + J];
        int labJ = (J < 5) ? sy[b * 5 + J] : qy[b];
        int labI = (I < 5) ? sy[b * 5 + I] : qy[b];
        float y = (labJ == labI) ? 1.f : 0.f;
        e = (p - y) * (p - y);
        float symv = 0.5f * (p + pt), antiv = 0.5f * (p - pt);
        atomicAdd(&s2[b], symv * symv);
        atomicAdd(&a2[b], antiv * antiv);
    }
    es[tid] = e;
    __syncthreads();
    for (int off = 128; off > 0; off >>= 1) {
        if (tid < off) es[tid] += es[tid + off];
        __syncthreads();
    }
    if (tid == 0) {
        float euc = es[0] / (float)NTASK;
        float sl = 0.f;
        for (int bb = 0; bb < 4; bb++) {
            float sn = sqrtf(s2[bb]), an = sqrtf(a2[bb]);
            sl += (sn - an) / (sn + an);
        }
        sl *= 0.25f;
        out[2] = sl;
        out[1] = euc - 0.1f * sl;
    }
}

// ---------------- launch ----------------
extern "C" void kernel_launch(void* const* d_in, const int* in_sizes, int n_in,
                              void* d_out, int out_size) {
    const float* sx   = (const float*)d_in[0];
    const int*   sy   = (const int*)  d_in[1];
    const float* qx   = (const float*)d_in[2];
    const int*   qy   = (const int*)  d_in[3];
    const float* k1   = (const float*)d_in[4];
    const float* bc1  = (const float*)d_in[5];
    const float* k2   = (const float*)d_in[6];
    const float* bc2  = (const float*)d_in[7];
    const float* k3   = (const float*)d_in[8];
    const float* bc3  = (const float*)d_in[9];
    const float* Wlog = (const float*)d_in[10];
    const float* blog = (const float*)d_in[11];
    const float* Wg1  = (const float*)d_in[12];
    const float* bg1  = (const float*)d_in[13];
    const float* Wg2  = (const float*)d_in[14];
    const float* bg2  = (const float*)d_in[15];
    const float* Wf1  = (const float*)d_in[16];
    const float* bf1  = (const float*)d_in[17];
    const float* Wf2  = (const float*)d_in[18];
    const float* bf2  = (const float*)d_in[19];
    float* out = (float*)d_out;

    // dynamic smem sizes (bytes)
    const int smem_c1  = (((3  * 65 * 65 + 3) & ~3) + 8 * 27 ) * 4;   //  ~51.6 KB
    const int smem_c2  = (((32 * 33 * 33 + 3) & ~3) + 8 * 288) * 4;   // ~148.6 KB
    const int smem_c3  = (48 * 17 * 17 + 48 * 9 * 32) * 4;            // ~110.8 KB
    const int smem_uv  = (64 * 68 + 2 * 66 * 64 + 64) * 4;            //  ~51.5 KB
    const int smem_rel = (3 * 8192 + 2048 + 64 + 16) * 4;             // ~106.8 KB

    cudaFuncSetAttribute(conv1_k,       cudaFuncAttributeMaxDynamicSharedMemorySize, smem_c1);
    cudaFuncSetAttribute(conv2_k,       cudaFuncAttributeMaxDynamicSharedMemorySize, smem_c2);
    cudaFuncSetAttribute(conv3_k,       cudaFuncAttributeMaxDynamicSharedMemorySize, smem_c3);
    cudaFuncSetAttribute(uv_kernel,     cudaFuncAttributeMaxDynamicSharedMemorySize, smem_uv);
    cudaFuncSetAttribute(relnet_kernel, cudaFuncAttributeMaxDynamicSharedMemorySize, smem_rel);

    pack_kernel<<<(NIMG * 12288 + 255) / 256, 256>>>(sx, qx);
    conv1_k<<<dim3(NIMG, 4), 256, smem_c1>>>(k1, bc1);
    conv2_k<<<dim3(NIMG, 6), 256, smem_c2>>>(k2, bc2);
    conv3_k<<<dim3(NIMG, 2), 256, smem_c3>>>(k3, bc3);
    logits_kernel<<<1, 256>>>(Wlog, blog, sy, qy, out);
    uv_kernel<<<dim3(NIMG, 2), 256, smem_uv>>>(Wg1, bg1);
    relnet_kernel<<<NTASK, 256, smem_rel>>>(Wg2, bg2, Wf1, bf1, Wf2, bf2);
    loss_kernel<<<1, 256>>>(sy, qy, out);
}

// round 16
// speedup vs baseline: 1.7465x; 1.7458x over previous
#include <cuda_runtime.h>
#include <math.h>
#include <stdint.h>

#define NIMG 24   // b*s = 4*6
#define NTASK 144 // b*s*s

// ---------------- device scratch (no allocations allowed) ----------------
__device__ float g_x [NIMG*3*64*64];
__device__ float g_f1[NIMG*32*32*32];
__device__ float g_f2[NIMG*48*16*16];
__device__ float g_f3[NIMG*64*64];     // [n][c][p], p = y*8+x
__device__ float g_ut[NIMG*64*128];    // [n][p][k]  u transposed (fp32)
__device__ float g_v [NIMG*64*128];    // [n][q][k]  (includes +bg1)
__device__ unsigned g_whi[64*64];      // Wg2 hi-bf16x2: [n][kpair]
__device__ unsigned g_wlo[64*64];      // Wg2 lo-bf16x2
__device__ float g_P [NTASK];

// ---------------- helpers ----------------
__device__ __forceinline__ unsigned pk_bf(float lo, float hi) {
    unsigned r;
    asm("cvt.rn.bf16x2.f32 %0, %1, %2;" : "=r"(r) : "f"(hi), "f"(lo));
    return r;   // low16 = lo, high16 = hi
}
// D(16x8,f32) += A(16x16,bf16) * B(16x8,bf16)  -- legacy tensor path, valid on sm_103
__device__ __forceinline__ void mma_bf16(float* d, unsigned a0, unsigned a1,
                                         unsigned a2, unsigned a3,
                                         unsigned b0, unsigned b1) {
    asm volatile(
        "mma.sync.aligned.m16n8k16.row.col.f32.bf16.bf16.f32 "
        "{%0,%1,%2,%3}, {%4,%5,%6,%7}, {%8,%9}, {%0,%1,%2,%3};"
        : "+f"(d[0]), "+f"(d[1]), "+f"(d[2]), "+f"(d[3])
        : "r"(a0), "r"(a1), "r"(a2), "r"(a3), "r"(b0), "r"(b1));
}

// ---------------- pack support_x / query_x into g_x ----------------
__global__ void pack_kernel(const float* __restrict__ sx, const float* __restrict__ qx) {
    int idx = blockIdx.x * blockDim.x + threadIdx.x;
    if (idx >= NIMG * 12288) return;
    int n = idx / 12288, r = idx - n * 12288;
    int b = n / 6, s = n - b * 6;
    g_x[idx] = (s < 5) ? sx[(b * 5 + s) * 12288 + r] : qx[b * 12288 + r];
}

// ---------------- generic stride-2 SAME 3x3 conv + relu ----------------
template<int CI, int HIN>
__device__ __forceinline__ void conv_body(const float* __restrict__ in,
                                          const float* __restrict__ wt,
                                          const float* __restrict__ bias,
                                          float* __restrict__ out, int CO) {
    constexpr int WIN = HIN, HOUT = HIN / 2, WOUT = HIN / 2;
    constexpr int PH = HIN + 1, PW = WIN + 1;
    constexpr int KK = CI * 9;
    constexpr int IN_ELEMS = CI * PH * PW;
    constexpr int WOFF = (IN_ELEMS + 3) & ~3;
    extern __shared__ float sm[];
    float* in_s = sm;
    float* w_s  = sm + WOFF;

    int n = blockIdx.x;
    int co0 = blockIdx.y * 8;
    int tid = threadIdx.x;

    for (int idx = tid; idx < IN_ELEMS; idx += blockDim.x) {
        int ci = idx / (PH * PW);
        int r = idx - ci * (PH * PW);
        int y = r / PW, x = r - y * PW;
        float v = 0.f;
        if (y < HIN && x < WIN) v = in[((n * CI + ci) * HIN + y) * WIN + x];
        in_s[idx] = v;
    }
    for (int idx = tid; idx < KK * 8; idx += blockDim.x) {
        int k = idx >> 3, c8 = idx & 7;
        w_s[idx] = wt[(co0 + c8) * KK + k];
    }
    __syncthreads();

    float bv[8];
    #pragma unroll
    for (int c8 = 0; c8 < 8; c8++) bv[c8] = bias[co0 + c8];

    for (int pos = tid; pos < HOUT * WOUT; pos += blockDim.x) {
        int y = pos / WOUT, x = pos - y * WOUT;
        float acc[8];
        #pragma unroll
        for (int c8 = 0; c8 < 8; c8++) acc[c8] = bv[c8];
        for (int ci = 0; ci < CI; ci++) {
            const float* ip = in_s + (ci * PH + 2 * y) * PW + 2 * x;
            #pragma unroll
            for (int kh = 0; kh < 3; kh++) {
                #pragma unroll
                for (int kw = 0; kw < 3; kw++) {
                    float iv = ip[kh * PW + kw];
                    int k = ci * 9 + kh * 3 + kw;
                    const float4 w0 = *(const float4*)(w_s + k * 8);
                    const float4 w1 = *(const float4*)(w_s + k * 8 + 4);
                    acc[0] = fmaf(iv, w0.x, acc[0]);
                    acc[1] = fmaf(iv, w0.y, acc[1]);
                    acc[2] = fmaf(iv, w0.z, acc[2]);
                    acc[3] = fmaf(iv, w0.w, acc[3]);
                    acc[4] = fmaf(iv, w1.x, acc[4]);
                    acc[5] = fmaf(iv, w1.y, acc[5]);
                    acc[6] = fmaf(iv, w1.z, acc[6]);
                    acc[7] = fmaf(iv, w1.w, acc[7]);
                }
            }
        }
        #pragma unroll
        for (int c8 = 0; c8 < 8; c8++)
            out[((n * CO + co0 + c8) * HOUT + y) * WOUT + x] = fmaxf(acc[c8], 0.f);
    }
}

__global__ void conv1_k(const float* wt, const float* b) { conv_body<3, 64>(g_x,  wt, b, g_f1, 32); }
__global__ void conv2_k(const float* wt, const float* b) { conv_body<32, 32>(g_f1, wt, b, g_f2, 48); }
__global__ void conv3_k(const float* wt, const float* b) { conv_body<48, 16>(g_f2, wt, b, g_f3, 64); }

// ---------------- logits + cls_loss ----------------
__global__ void logits_kernel(const float* __restrict__ Wlog, const float* __restrict__ blog,
                              const int* __restrict__ sy, const int* __restrict__ qy,
                              float* __restrict__ out) {
    __shared__ float pooled[NIMG * 64];
    __shared__ float lg[NIMG * 64];
    __shared__ float lps[NIMG];
    int tid = threadIdx.x;
    for (int idx = tid; idx < NIMG * 64; idx += 256) {
        const float* f = g_f3 + idx * 64;
        float s = 0.f;
        #pragma unroll 4
        for (int p = 0; p < 64; p++) s += f[p];
        pooled[idx] = s * (1.f / 64.f);
    }
    __syncthreads();
    for (int idx = tid; idx < NIMG * 64; idx += 256) {
        int n = idx >> 6, cl = idx & 63;
        const float* pn = pooled + n * 64;
        float s = blog[cl];
        for (int c = 0; c < 64; c++) s = fmaf(pn[c], Wlog[c * 64 + cl], s);
        lg[idx] = s;
    }
    __syncthreads();
    if (tid < NIMG) {
        int n = tid, b = n / 6, ss = n - b * 6;
        int lab = (ss < 5) ? sy[b * 5 + ss] : qy[b];
        const float* l = lg + n * 64;
        float m = l[0];
        for (int c = 1; c < 64; c++) m = fmaxf(m, l[c]);
        float se = 0.f;
        for (int c = 0; c < 64; c++) se += expf(l[c] - m);
        lps[n] = l[lab] - m - logf(se);
    }
    __syncthreads();
    if (tid == 0) {
        float s = 0.f;
        for (int n = 0; n < NIMG; n++) s += lps[n];
        out[0] = -s / (float)NIMG;
    }
}

// ---------------- u = a@W1a (transposed out), v = a@W1b + bg1 ----------------
__global__ void uv_kernel(const float* __restrict__ Wg1, const float* __restrict__ bg1) {
    extern __shared__ float sm[];
    float* a_s  = sm;                 // [64][68]
    float* wa_s = sm + 64 * 68;       // [66][64]
    float* wb_s = wa_s + 66 * 64;     // [66][64]
    float* bgs  = wb_s + 66 * 64;     // [64]
    int n = blockIdx.x;
    int k0 = blockIdx.y * 64;
    int tid = threadIdx.x;

    for (int idx = tid; idx < 64 * 64; idx += 256) {
        int c = idx >> 6, p = idx & 63;
        a_s[p * 68 + c] = g_f3[(n * 64 + c) * 64 + p];
    }
    for (int idx = tid; idx < 66 * 64; idx += 256) {
        int c = idx >> 6, kk = idx & 63;
        wa_s[idx] = Wg1[c * 128 + k0 + kk];
        wb_s[idx] = Wg1[(66 + c) * 128 + k0 + kk];
    }
    if (tid < 64) {
        bgs[tid] = bg1[k0 + tid];
        int p = tid;
        a_s[p * 68 + 64] = (float)(p >> 3) * 0.125f;
        a_s[p * 68 + 65] = (float)(p & 7) * 0.125f;
    }
    __syncthreads();

    int kg = tid & 7, pgg = tid >> 3;
    int p0 = pgg * 2, kb = kg * 8;
    float ua[2][8], va[2][8];
    #pragma unroll
    for (int kk = 0; kk < 8; kk++) {
        ua[0][kk] = 0.f; ua[1][kk] = 0.f;
        va[0][kk] = bgs[kb + kk]; va[1][kk] = bgs[kb + kk];
    }
    for (int c = 0; c < 66; c++) {
        float a0 = a_s[p0 * 68 + c];
        float a1 = a_s[(p0 + 1) * 68 + c];
        float4 w0 = *(const float4*)(wa_s + c * 64 + kb);
        float4 w1 = *(const float4*)(wa_s + c * 64 + kb + 4);
        float4 x0 = *(const float4*)(wb_s + c * 64 + kb);
        float4 x1 = *(const float4*)(wb_s + c * 64 + kb + 4);
        float wv[8] = {w0.x, w0.y, w0.z, w0.w, w1.x, w1.y, w1.z, w1.w};
        float xv[8] = {x0.x, x0.y, x0.z, x0.w, x1.x, x1.y, x1.z, x1.w};
        #pragma unroll
        for (int kk = 0; kk < 8; kk++) {
            ua[0][kk] = fmaf(a0, wv[kk], ua[0][kk]);
            ua[1][kk] = fmaf(a1, wv[kk], ua[1][kk]);
            va[0][kk] = fmaf(a0, xv[kk], va[0][kk]);
            va[1][kk] = fmaf(a1, xv[kk], va[1][kk]);
        }
    }
    #pragma unroll
    for (int tp = 0; tp < 2; tp++)
        #pragma unroll
        for (int kk = 0; kk < 8; kk++) {
            int gk = k0 + kb + kk;
            g_ut[(n * 64 + p0 + tp) * 128 + gk] = ua[tp][kk];
            g_v [(n * 64 + p0 + tp) * 128 + gk] = va[tp][kk];
        }
}

// ---------------- Wg2 split into bf16 hi/lo as bf16x2 [n][kpair] ----------------
__global__ void wprep_kernel(const float* __restrict__ Wg2) {
    int idx = blockIdx.x * 256 + threadIdx.x;   // 4096 = 64 n x 64 k-pairs
    if (idx >= 4096) return;
    int n = idx >> 6, kp = idx & 63;
    int k = kp * 2;
    float w0 = Wg2[k * 64 + n], w1 = Wg2[(k + 1) * 64 + n];
    unsigned hi2 = pk_bf(w0, w1);
    float f0 = __uint_as_float(hi2 << 16);
    float f1 = __uint_as_float(hi2 & 0xffff0000u);
    unsigned lo2 = pk_bf(w0 - f0, w1 - f1);
    g_whi[n * 64 + kp] = hi2;
    g_wlo[n * 64 + kp] = lo2;
}

// ---------------- relnet: bf16-split mma.sync GEMM, one CTA per task ----------------
#define PADK 132
#define PADW 68

__global__ void __launch_bounds__(256, 1)
relnet_kernel(const float* __restrict__ bg2,
              const float* __restrict__ Wf1, const float* __restrict__ bf1,
              const float* __restrict__ Wf2, const float* __restrict__ bf2) {
    extern __shared__ float sm[];
    float*    us    = sm;                          // [64][132]
    float*    vs    = us + 64 * PADK;              // [64][132]
    unsigned* whi_s = (unsigned*)(vs + 64 * PADK); // [64][68]
    unsigned* wlo_s = whi_s + 64 * PADW;           // [64][68]
    float*    red   = (float*)(wlo_s + 64 * PADW); // [8][64]
    float*    xf    = red + 8 * 64;                // [64]
    float*    hsm   = xf + 64;                     // [16]

    int task = blockIdx.x;
    int b = task / 36, rem = task - b * 36;
    int J = rem / 6, I = rem - J * 6;
    int ni = b * 6 + I, nj = b * 6 + J;
    int tid = threadIdx.x;
    int wid = tid >> 5, l = tid & 31;
    int g = l & 3, r0 = l >> 2;

    for (int idx = tid; idx < 8192; idx += 256) {
        int p = idx >> 7, k = idx & 127;
        us[p * PADK + k] = g_ut[ni * 8192 + idx];
        vs[p * PADK + k] = g_v [nj * 8192 + idx];
    }
    for (int idx = tid; idx < 4096; idx += 256) {
        int n = idx >> 6, kp = idx & 63;
        whi_s[n * PADW + kp] = g_whi[idx];
        wlo_s[n * PADW + kp] = g_wlo[idx];
    }
    __syncthreads();

    // per-thread output columns: c = n*8 + g*2 + {0,1}  (D fragment cols keyed by g)
    float bgr[16];
    #pragma unroll
    for (int n = 0; n < 8; n++) {
        bgr[n * 2]     = bg2[n * 8 + g * 2];
        bgr[n * 2 + 1] = bg2[n * 8 + g * 2 + 1];
    }
    float acc16[16];
    #pragma unroll
    for (int t = 0; t < 16; t++) acc16[t] = 0.f;

    for (int qi = 0; qi < 8; ++qi) {
        int q = qi * 8 + wid;
        const float* vrow = vs + q * PADK;
        for (int mt = 0; mt < 4; ++mt) {
            const float* u0 = us + (mt * 16 + r0) * PADK;
            const float* u1 = u0 + 8 * PADK;

            float D[8][4];
            #pragma unroll
            for (int n = 0; n < 8; n++)
                #pragma unroll
                for (int j = 0; j < 4; j++) D[n][j] = 0.f;

            #pragma unroll
            for (int k = 0; k < 8; ++k) {
                int c0 = k * 16 + g * 2;
                float2 uaa = *(const float2*)(u0 + c0);
                float2 uab = *(const float2*)(u1 + c0);
                float2 uac = *(const float2*)(u0 + c0 + 8);
                float2 uad = *(const float2*)(u1 + c0 + 8);
                float2 va  = *(const float2*)(vrow + c0);
                float2 vb  = *(const float2*)(vrow + c0 + 8);

                float h0 = fmaxf(uaa.x + va.x, 0.f), h1 = fmaxf(uaa.y + va.y, 0.f);
                float h2 = fmaxf(uab.x + va.x, 0.f), h3 = fmaxf(uab.y + va.y, 0.f);
                float h4 = fmaxf(uac.x + vb.x, 0.f), h5 = fmaxf(uac.y + vb.y, 0.f);
                float h6 = fmaxf(uad.x + vb.x, 0.f), h7 = fmaxf(uad.y + vb.y, 0.f);

                unsigned ahi0 = pk_bf(h0, h1), ahi1 = pk_bf(h2, h3);
                unsigned ahi2 = pk_bf(h4, h5), ahi3 = pk_bf(h6, h7);
                unsigned alo0 = pk_bf(h0 - __uint_as_float(ahi0 << 16),
                                      h1 - __uint_as_float(ahi0 & 0xffff0000u));
                unsigned alo1 = pk_bf(h2 - __uint_as_float(ahi1 << 16),
                                      h3 - __uint_as_float(ahi1 & 0xffff0000u));
                unsigned alo2 = pk_bf(h4 - __uint_as_float(ahi2 << 16),
                                      h5 - __uint_as_float(ahi2 & 0xffff0000u));
                unsigned alo3 = pk_bf(h6 - __uint_as_float(ahi3 << 16),
                                      h7 - __uint_as_float(ahi3 & 0xffff0000u));

                // B fragment: col n = lane>>2 (r0), row k = (lane&3)*2 (g) -- kpair = k*8+g
                int wb = k * 8 + g;
                #pragma unroll
                for (int n = 0; n < 8; ++n) {
                    int ch = n * 8 + r0;   // output channel for this lane's B regs
                    unsigned bh0 = whi_s[ch * PADW + wb];
                    unsigned bh1 = whi_s[ch * PADW + wb + 4];
                    unsigned bl0 = wlo_s[ch * PADW + wb];
                    unsigned bl1 = wlo_s[ch * PADW + wb + 4];
                    mma_bf16(D[n], ahi0, ahi1, ahi2, ahi3, bh0, bh1);
                    mma_bf16(D[n], alo0, alo1, alo2, alo3, bh0, bh1);
                    mma_bf16(D[n], ahi0, ahi1, ahi2, ahi3, bl0, bl1);
                }
            }

            #pragma unroll
            for (int n = 0; n < 8; ++n) {
                acc16[n * 2]     += fmaxf(D[n][0] + bgr[n * 2],     0.f)
                                  + fmaxf(D[n][2] + bgr[n * 2],     0.f);
                acc16[n * 2 + 1] += fmaxf(D[n][1] + bgr[n * 2 + 1], 0.f)
                                  + fmaxf(D[n][3] + bgr[n * 2 + 1], 0.f);
            }
        }
    }

    // reduce lanes with same g (bits 0-1 preserved by xor 16/8/4)
    #pragma unroll
    for (int t = 0; t < 16; t++) {
        acc16[t] += __shfl_xor_sync(0xffffffffu, acc16[t], 16);
        acc16[t] += __shfl_xor_sync(0xffffffffu, acc16[t], 8);
        acc16[t] += __shfl_xor_sync(0xffffffffu, acc16[t], 4);
    }
    if (l < 4) {
        #pragma unroll
        for (int n = 0; n < 8; n++) {
            red[wid * 64 + n * 8 + l * 2]     = acc16[n * 2];
            red[wid * 64 + n * 8 + l * 2 + 1] = acc16[n * 2 + 1];
        }
    }
    __syncthreads();

    if (tid < 64) {
        float s = 0.f;
        #pragma unroll
        for (int w = 0; w < 8; w++) s += red[w * 64 + tid];
        xf[tid] = s;
    }
    __syncthreads();
    if (tid < 16) {
        float s = bf1[tid];
        for (int c = 0; c < 64; c++) s = fmaf(xf[c], Wf1[c * 16 + tid], s);
        hsm[tid] = fmaxf(s, 0.f);
    }
    __syncthreads();
    if (tid == 0) {
        float s = bf2[0];
        for (int t = 0; t < 16; t++) s = fmaf(hsm[t], Wf2[t], s);
        g_P[task] = 1.f / (1.f + expf(-s));
    }
}

// ---------------- final losses ----------------
__global__ void loss_kernel(const int* __restrict__ sy, const int* __restrict__ qy,
                            float* __restrict__ out) {
    __shared__ float es[256];
    __shared__ float s2[4], a2[4];
    int tid = threadIdx.x;
    if (tid < 4) { s2[tid] = 0.f; a2[tid] = 0.f; }
    __syncthreads();
    float e = 0.f;
    if (tid < NTASK) {
        int b = tid / 36, r = tid - b * 36;
        int J = r / 6, I = r - J * 6;
        float p  = g_P[tid];
        float pt = g_P[b * 36 + I * 6 + J];
        int labJ = (J < 5) ? sy[b * 5 + J] : qy[b];
        int labI = (I < 5) ? sy[b * 5 + I] : qy[b];
        float y = (labJ == labI) ? 1.f : 0.f;
        e = (p - y) * (p - y);
        float symv = 0.5f * (p + pt), antiv = 0.5f * (p - pt);
        atomicAdd(&s2[b], symv * symv);
        atomicAdd(&a2[b], antiv * antiv);
    }
    es[tid] = e;
    __syncthreads();
    for (int off = 128; off > 0; off >>= 1) {
        if (tid < off) es[tid] += es[tid + off];
        __syncthreads();
    }
    if (tid == 0) {
        float euc = es[0] / (float)NTASK;
        float sl = 0.f;
        for (int bb = 0; bb < 4; bb++) {
            float sn = sqrtf(s2[bb]), an = sqrtf(a2[bb]);
            sl += (sn - an) / (sn + an);
        }
        sl *= 0.25f;
        out[2] = sl;
        out[1] = euc - 0.1f * sl;
    }
}

// ---------------- launch ----------------
extern "C" void kernel_launch(void* const* d_in, const int* in_sizes, int n_in,
                              void* d_out, int out_size) {
    const float* sx   = (const float*)d_in[0];
    const int*   sy   = (const int*)  d_in[1];
    const float* qx   = (const float*)d_in[2];
    const int*   qy   = (const int*)  d_in[3];
    const float* k1   = (const float*)d_in[4];
    const float* bc1  = (const float*)d_in[5];
    const float* k2   = (const float*)d_in[6];
    const float* bc2  = (const float*)d_in[7];
    const float* k3   = (const float*)d_in[8];
    const float* bc3  = (const float*)d_in[9];
    const float* Wlog = (const float*)d_in[10];
    const float* blog = (const float*)d_in[11];
    const float* Wg1  = (const float*)d_in[12];
    const float* bg1  = (const float*)d_in[13];
    const float* Wg2  = (const float*)d_in[14];
    const float* bg2  = (const float*)d_in[15];
    const float* Wf1  = (const float*)d_in[16];
    const float* bf1  = (const float*)d_in[17];
    const float* Wf2  = (const float*)d_in[18];
    const float* bf2  = (const float*)d_in[19];
    float* out = (float*)d_out;

    const int smem_c1  = (((3  * 65 * 65 + 3) & ~3) + 8 * 27 ) * 4;
    const int smem_c2  = (((32 * 33 * 33 + 3) & ~3) + 8 * 288) * 4;
    const int smem_c3  = (((48 * 17 * 17 + 3) & ~3) + 8 * 432) * 4;
    const int smem_uv  = (64 * 68 + 2 * 66 * 64 + 64) * 4;
    const int smem_rel = (2 * 64 * PADK + 2 * 64 * PADW + 8 * 64 + 64 + 16) * 4; // ~104.8 KB

    cudaFuncSetAttribute(conv1_k,       cudaFuncAttributeMaxDynamicSharedMemorySize, smem_c1);
    cudaFuncSetAttribute(conv2_k,       cudaFuncAttributeMaxDynamicSharedMemorySize, smem_c2);
    cudaFuncSetAttribute(conv3_k,       cudaFuncAttributeMaxDynamicSharedMemorySize, smem_c3);
    cudaFuncSetAttribute(uv_kernel,     cudaFuncAttributeMaxDynamicSharedMemorySize, smem_uv);
    cudaFuncSetAttribute(relnet_kernel, cudaFuncAttributeMaxDynamicSharedMemorySize, smem_rel);

    pack_kernel<<<(NIMG * 12288 + 255) / 256, 256>>>(sx, qx);
    wprep_kernel<<<16, 256>>>(Wg2);
    conv1_k<<<dim3(NIMG, 4), 256, smem_c1>>>(k1, bc1);
    conv2_k<<<dim3(NIMG, 6), 256, smem_c2>>>(k2, bc2);
    conv3_k<<<dim3(NIMG, 8), 256, smem_c3>>>(k3, bc3);
    logits_kernel<<<1, 256>>>(Wlog, blog, sy, qy, out);
    uv_kernel<<<dim3(NIMG, 2), 256, smem_uv>>>(Wg1, bg1);
    relnet_kernel<<<NTASK, 256, smem_rel>>>(bg2, Wf1, bf1, Wf2, bf2);
    loss_kernel<<<1, 256>>>(sy, qy, out);
}

// round 17
// speedup vs baseline: 2.2590x; 1.2935x over previous
#include <cuda_runtime.h>
#include <math.h>
#include <stdint.h>

#define NIMG 24   // b*s = 4*6
#define NTASK 144 // b*s*s

// ---------------- device scratch (no allocations allowed) ----------------
__device__ float g_f1[NIMG*32*32*32];
__device__ float g_f2[NIMG*48*16*16];
__device__ float g_f3[NIMG*64*64];     // [n][c][p], p = y*8+x
__device__ float g_ut[NIMG*64*128];    // [n][p][k]  u transposed (fp32)
__device__ float g_v [NIMG*64*128];    // [n][q][k]  (includes +bg1)
__device__ unsigned g_whi[64*64];      // Wg2 hi-bf16x2: [n][kpair]
__device__ unsigned g_wlo[64*64];      // Wg2 lo-bf16x2
__device__ float g_lps[NIMG];          // per-image log-prob of label
__device__ float g_P [NTASK];          // score[b][J][I]

// ---------------- helpers ----------------
__device__ __forceinline__ unsigned pk_bf(float lo, float hi) {
    unsigned r;
    asm("cvt.rn.bf16x2.f32 %0, %1, %2;" : "=r"(r) : "f"(hi), "f"(lo));
    return r;   // low16 = lo, high16 = hi
}
// D(16x8,f32) += A(16x16,bf16) * B(16x8,bf16)  -- legacy tensor path, valid on sm_103
__device__ __forceinline__ void mma_bf16(float* d, unsigned a0, unsigned a1,
                                         unsigned a2, unsigned a3,
                                         unsigned b0, unsigned b1) {
    asm volatile(
        "mma.sync.aligned.m16n8k16.row.col.f32.bf16.bf16.f32 "
        "{%0,%1,%2,%3}, {%4,%5,%6,%7}, {%8,%9}, {%0,%1,%2,%3};"
        : "+f"(d[0]), "+f"(d[1]), "+f"(d[2]), "+f"(d[3])
        : "r"(a0), "r"(a1), "r"(a2), "r"(a3), "r"(b0), "r"(b1));
}

// ---------------- conv compute core (ILP-friendly) ----------------
template<int CI, int PH, int PW, int HOUT, int WOUT>
__device__ __forceinline__ void conv_compute(const float* __restrict__ in_s,
                                             const float* __restrict__ w_s,
                                             const float* __restrict__ bias,
                                             float* __restrict__ out,
                                             int n, int co0, int CO, int tid, int nthr) {
    float bv[8];
    #pragma unroll
    for (int c8 = 0; c8 < 8; c8++) bv[c8] = bias[co0 + c8];

    for (int pos = tid; pos < HOUT * WOUT; pos += nthr) {
        int y = pos / WOUT, x = pos - y * WOUT;
        float acc[8];
        #pragma unroll
        for (int c8 = 0; c8 < 8; c8++) acc[c8] = bv[c8];
        #pragma unroll 2
        for (int ci = 0; ci < CI; ci++) {
            const float* ip = in_s + (ci * PH + 2 * y) * PW + 2 * x;
            float iv[9];
            #pragma unroll
            for (int kh = 0; kh < 3; kh++)
                #pragma unroll
                for (int kw = 0; kw < 3; kw++)
                    iv[kh * 3 + kw] = ip[kh * PW + kw];
            const float* wk = w_s + ci * 72;
            #pragma unroll
            for (int t = 0; t < 9; t++) {
                const float4 w0 = *(const float4*)(wk + t * 8);
                const float4 w1 = *(const float4*)(wk + t * 8 + 4);
                acc[0] = fmaf(iv[t], w0.x, acc[0]);
                acc[1] = fmaf(iv[t], w0.y, acc[1]);
                acc[2] = fmaf(iv[t], w0.z, acc[2]);
                acc[3] = fmaf(iv[t], w0.w, acc[3]);
                acc[4] = fmaf(iv[t], w1.x, acc[4]);
                acc[5] = fmaf(iv[t], w1.y, acc[5]);
                acc[6] = fmaf(iv[t], w1.z, acc[6]);
                acc[7] = fmaf(iv[t], w1.w, acc[7]);
            }
        }
        #pragma unroll
        for (int c8 = 0; c8 < 8; c8++)
            out[((n * CO + co0 + c8) * HOUT + y) * WOUT + x] = fmaxf(acc[c8], 0.f);
    }
}

// ---------------- conv1: reads support_x / query_x directly (pack fused) ----------------
__global__ void __launch_bounds__(256, 1)
conv1_k(const float* __restrict__ sx, const float* __restrict__ qx,
        const float* __restrict__ wt, const float* __restrict__ bias) {
    constexpr int CI = 3, HIN = 64, PH = 65, PW = 65, KK = 27;
    constexpr int IN_ELEMS = CI * PH * PW;
    constexpr int WOFF = (IN_ELEMS + 3) & ~3;
    extern __shared__ float sm[];
    float* in_s = sm;
    float* w_s  = sm + WOFF;
    int n = blockIdx.x;
    int co0 = blockIdx.y * 8;
    int tid = threadIdx.x;
    int b = n / 6, s = n - b * 6;
    const float* img = (s < 5) ? sx + (b * 5 + s) * 12288 : qx + b * 12288;

    for (int idx = tid; idx < IN_ELEMS; idx += 256) {
        int ci = idx / (PH * PW);
        int r = idx - ci * (PH * PW);
        int y = r / PW, x = r - y * PW;
        float v = 0.f;
        if (y < HIN && x < HIN) v = img[ci * 4096 + y * 64 + x];
        in_s[idx] = v;
    }
    for (int idx = tid; idx < KK * 8; idx += 256) {
        int k = idx >> 3, c8 = idx & 7;
        w_s[idx] = wt[(co0 + c8) * KK + k];
    }
    __syncthreads();
    conv_compute<CI, PH, PW, 32, 32>(in_s, w_s, bias, g_f1, n, co0, 32, tid, 256);
}

// ---------------- conv2 / conv3: staged from device scratch ----------------
template<int CI, int HIN>
__device__ __forceinline__ void conv_body(const float* __restrict__ in,
                                          const float* __restrict__ wt,
                                          const float* __restrict__ bias,
                                          float* __restrict__ out, int CO) {
    constexpr int PH = HIN + 1, PW = HIN + 1;
    constexpr int KK = CI * 9;
    constexpr int IN_ELEMS = CI * PH * PW;
    constexpr int WOFF = (IN_ELEMS + 3) & ~3;
    extern __shared__ float sm[];
    float* in_s = sm;
    float* w_s  = sm + WOFF;
    int n = blockIdx.x;
    int co0 = blockIdx.y * 8;
    int tid = threadIdx.x;

    for (int idx = tid; idx < IN_ELEMS; idx += 256) {
        int ci = idx / (PH * PW);
        int r = idx - ci * (PH * PW);
        int y = r / PW, x = r - y * PW;
        float v = 0.f;
        if (y < HIN && x < HIN) v = in[((n * CI + ci) * HIN + y) * HIN + x];
        in_s[idx] = v;
    }
    for (int idx = tid; idx < KK * 8; idx += 256) {
        int k = idx >> 3, c8 = idx & 7;
        w_s[idx] = wt[(co0 + c8) * KK + k];
    }
    __syncthreads();
    conv_compute<CI, PH, PW, HIN/2, HIN/2>(in_s, w_s, bias, out, n, co0, CO, tid, 256);
}

__global__ void __launch_bounds__(256, 1)
conv2_k(const float* wt, const float* b) { conv_body<32, 32>(g_f1, wt, b, g_f2, 48); }
__global__ void __launch_bounds__(256, 1)
conv3_k(const float* wt, const float* b) { conv_body<48, 16>(g_f2, wt, b, g_f3, 64); }

// ---------------- logits per image (24 CTAs) ----------------
__global__ void logits_kernel(const float* __restrict__ Wlog, const float* __restrict__ blog,
                              const int* __restrict__ sy, const int* __restrict__ qy) {
    __shared__ float pooled[64];
    __shared__ float lg[64];
    int n = blockIdx.x;
    int tid = threadIdx.x;
    if (tid < 64) {
        const float* f = g_f3 + (n * 64 + tid) * 64;
        float s = 0.f;
        #pragma unroll 4
        for (int p = 0; p < 64; p++) s += f[p];
        pooled[tid] = s * (1.f / 64.f);
    }
    __syncthreads();
    if (tid < 64) {
        float s = blog[tid];
        for (int c = 0; c < 64; c++) s = fmaf(pooled[c], Wlog[c * 64 + tid], s);
        lg[tid] = s;
    }
    __syncthreads();
    if (tid == 0) {
        int b = n / 6, ss = n - b * 6;
        int lab = (ss < 5) ? sy[b * 5 + ss] : qy[b];
        float m = lg[0];
        for (int c = 1; c < 64; c++) m = fmaxf(m, lg[c]);
        float se = 0.f;
        for (int c = 0; c < 64; c++) se += expf(lg[c] - m);
        g_lps[n] = lg[lab] - m - logf(se);
    }
}

// ---------------- u = a@W1a (transposed out), v = a@W1b + bg1 ----------------
__global__ void __launch_bounds__(256, 1)
uv_kernel(const float* __restrict__ Wg1, const float* __restrict__ bg1) {
    extern __shared__ float sm[];
    float* a_s  = sm;                 // [64][68]
    float* wa_s = sm + 64 * 68;       // [66][64]
    float* wb_s = wa_s + 66 * 64;     // [66][64]
    float* bgs  = wb_s + 66 * 64;     // [64]
    int n = blockIdx.x;
    int k0 = blockIdx.y * 64;
    int tid = threadIdx.x;

    for (int idx = tid; idx < 64 * 64; idx += 256) {
        int c = idx >> 6, p = idx & 63;
        a_s[p * 68 + c] = g_f3[(n * 64 + c) * 64 + p];
    }
    for (int idx = tid; idx < 66 * 64; idx += 256) {
        int c = idx >> 6, kk = idx & 63;
        wa_s[idx] = Wg1[c * 128 + k0 + kk];
        wb_s[idx] = Wg1[(66 + c) * 128 + k0 + kk];
    }
    if (tid < 64) {
        bgs[tid] = bg1[k0 + tid];
        int p = tid;
        a_s[p * 68 + 64] = (float)(p >> 3) * 0.125f;
        a_s[p * 68 + 65] = (float)(p & 7) * 0.125f;
    }
    __syncthreads();

    int kg = tid & 7, pgg = tid >> 3;
    int p0 = pgg * 2, kb = kg * 8;
    float ua[2][8], va[2][8];
    #pragma unroll
    for (int kk = 0; kk < 8; kk++) {
        ua[0][kk] = 0.f; ua[1][kk] = 0.f;
        va[0][kk] = bgs[kb + kk]; va[1][kk] = bgs[kb + kk];
    }
    for (int c = 0; c < 66; c++) {
        float a0 = a_s[p0 * 68 + c];
        float a1 = a_s[(p0 + 1) * 68 + c];
        float4 w0 = *(const float4*)(wa_s + c * 64 + kb);
        float4 w1 = *(const float4*)(wa_s + c * 64 + kb + 4);
        float4 x0 = *(const float4*)(wb_s + c * 64 + kb);
        float4 x1 = *(const float4*)(wb_s + c * 64 + kb + 4);
        float wv[8] = {w0.x, w0.y, w0.z, w0.w, w1.x, w1.y, w1.z, w1.w};
        float xv[8] = {x0.x, x0.y, x0.z, x0.w, x1.x, x1.y, x1.z, x1.w};
        #pragma unroll
        for (int kk = 0; kk < 8; kk++) {
            ua[0][kk] = fmaf(a0, wv[kk], ua[0][kk]);
            ua[1][kk] = fmaf(a1, wv[kk], ua[1][kk]);
            va[0][kk] = fmaf(a0, xv[kk], va[0][kk]);
            va[1][kk] = fmaf(a1, xv[kk], va[1][kk]);
        }
    }
    #pragma unroll
    for (int tp = 0; tp < 2; tp++)
        #pragma unroll
        for (int kk = 0; kk < 8; kk++) {
            int gk = k0 + kb + kk;
            g_ut[(n * 64 + p0 + tp) * 128 + gk] = ua[tp][kk];
            g_v [(n * 64 + p0 + tp) * 128 + gk] = va[tp][kk];
        }
}

// ---------------- Wg2 split into bf16 hi/lo as bf16x2 [n][kpair] ----------------
__global__ void wprep_kernel(const float* __restrict__ Wg2) {
    int idx = blockIdx.x * 256 + threadIdx.x;   // 4096 = 64 n x 64 k-pairs
    if (idx >= 4096) return;
    int n = idx >> 6, kp = idx & 63;
    int k = kp * 2;
    float w0 = Wg2[k * 64 + n], w1 = Wg2[(k + 1) * 64 + n];
    unsigned hi2 = pk_bf(w0, w1);
    float f0 = __uint_as_float(hi2 << 16);
    float f1 = __uint_as_float(hi2 & 0xffff0000u);
    unsigned lo2 = pk_bf(w0 - f0, w1 - f1);
    g_whi[n * 64 + kp] = hi2;
    g_wlo[n * 64 + kp] = lo2;
}

// ---------------- relnet: bf16-split mma.sync GEMM, one CTA per task ----------------
#define PADK 132
#define PADW 68

__global__ void __launch_bounds__(256, 1)
relnet_kernel(const float* __restrict__ bg2,
              const float* __restrict__ Wf1, const float* __restrict__ bf1,
              const float* __restrict__ Wf2, const float* __restrict__ bf2) {
    extern __shared__ float sm[];
    float*    us    = sm;                          // [64][132]
    float*    vs    = us + 64 * PADK;              // [64][132]
    unsigned* whi_s = (unsigned*)(vs + 64 * PADK); // [64][68]
    unsigned* wlo_s = whi_s + 64 * PADW;           // [64][68]
    float*    red   = (float*)(wlo_s + 64 * PADW); // [8][64]
    float*    xf    = red + 8 * 64;                // [64]
    float*    hsm   = xf + 64;                     // [16]

    int task = blockIdx.x;
    int b = task / 36, rem = task - b * 36;
    int J = rem / 6, I = rem - J * 6;
    int ni = b * 6 + I, nj = b * 6 + J;
    int tid = threadIdx.x;
    int wid = tid >> 5, l = tid & 31;
    int g = l & 3, r0 = l >> 2;

    for (int idx = tid; idx < 8192; idx += 256) {
        int p = idx >> 7, k = idx & 127;
        us[p * PADK + k] = g_ut[ni * 8192 + idx];
        vs[p * PADK + k] = g_v [nj * 8192 + idx];
    }
    for (int idx = tid; idx < 4096; idx += 256) {
        int n = idx >> 6, kp = idx & 63;
        whi_s[n * PADW + kp] = g_whi[idx];
        wlo_s[n * PADW + kp] = g_wlo[idx];
    }
    __syncthreads();

    // per-thread output columns: c = n*8 + g*2 + {0,1}  (D fragment cols keyed by g)
    float bgr[16];
    #pragma unroll
    for (int n = 0; n < 8; n++) {
        bgr[n * 2]     = bg2[n * 8 + g * 2];
        bgr[n * 2 + 1] = bg2[n * 8 + g * 2 + 1];
    }
    float acc16[16];
    #pragma unroll
    for (int t = 0; t < 16; t++) acc16[t] = 0.f;

    for (int qi = 0; qi < 8; ++qi) {
        int q = qi * 8 + wid;
        const float* vrow = vs + q * PADK;
        for (int mt = 0; mt < 4; ++mt) {
            const float* u0 = us + (mt * 16 + r0) * PADK;
            const float* u1 = u0 + 8 * PADK;

            float D[8][4];
            #pragma unroll
            for (int n = 0; n < 8; n++)
                #pragma unroll
                for (int j = 0; j < 4; j++) D[n][j] = 0.f;

            #pragma unroll
            for (int k = 0; k < 8; ++k) {
                int c0 = k * 16 + g * 2;
                float2 uaa = *(const float2*)(u0 + c0);
                float2 uab = *(const float2*)(u1 + c0);
                float2 uac = *(const float2*)(u0 + c0 + 8);
                float2 uad = *(const float2*)(u1 + c0 + 8);
                float2 va  = *(const float2*)(vrow + c0);
                float2 vb  = *(const float2*)(vrow + c0 + 8);

                float h0 = fmaxf(uaa.x + va.x, 0.f), h1 = fmaxf(uaa.y + va.y, 0.f);
                float h2 = fmaxf(uab.x + va.x, 0.f), h3 = fmaxf(uab.y + va.y, 0.f);
                float h4 = fmaxf(uac.x + vb.x, 0.f), h5 = fmaxf(uac.y + vb.y, 0.f);
                float h6 = fmaxf(uad.x + vb.x, 0.f), h7 = fmaxf(uad.y + vb.y, 0.f);

                unsigned ahi0 = pk_bf(h0, h1), ahi1 = pk_bf(h2, h3);
                unsigned ahi2 = pk_bf(h4, h5), ahi3 = pk_bf(h6, h7);
                unsigned alo0 = pk_bf(h0 - __uint_as_float(ahi0 << 16),
                                      h1 - __uint_as_float(ahi0 & 0xffff0000u));
                unsigned alo1 = pk_bf(h2 - __uint_as_float(ahi1 << 16),
                                      h3 - __uint_as_float(ahi1 & 0xffff0000u));
                unsigned alo2 = pk_bf(h4 - __uint_as_float(ahi2 << 16),
                                      h5 - __uint_as_float(ahi2 & 0xffff0000u));
                unsigned alo3 = pk_bf(h6 - __uint_as_float(ahi3 << 16),
                                      h7 - __uint_as_float(ahi3 & 0xffff0000u));

                // B fragment: col n = lane>>2 (r0), row k = (lane&3)*2 (g) -- kpair = k*8+g
                int wb = k * 8 + g;
                #pragma unroll
                for (int n = 0; n < 8; ++n) {
                    int ch = n * 8 + r0;   // output channel for this lane's B regs
                    unsigned bh0 = whi_s[ch * PADW + wb];
                    unsigned bh1 = whi_s[ch * PADW + wb + 4];
                    unsigned bl0 = wlo_s[ch * PADW + wb];
                    unsigned bl1 = wlo_s[ch * PADW + wb + 4];
                    mma_bf16(D[n], ahi0, ahi1, ahi2, ahi3, bh0, bh1);
                    mma_bf16(D[n], alo0, alo1, alo2, alo3, bh0, bh1);
                    mma_bf16(D[n], ahi0, ahi1, ahi2, ahi3, bl0, bl1);
                }
            }

            #pragma unroll
            for (int n = 0; n < 8; ++n) {
                acc16[n * 2]     += fmaxf(D[n][0] + bgr[n * 2],     0.f)
                                  + fmaxf(D[n][2] + bgr[n * 2],     0.f);
                acc16[n * 2 + 1] += fmaxf(D[n][1] + bgr[n * 2 + 1], 0.f)
                                  + fmaxf(D[n][3] + bgr[n * 2 + 1], 0.f);
            }
        }
    }

    // reduce lanes with same g (bits 0-1 preserved by xor 16/8/4)
    #pragma unroll
    for (int t = 0; t < 16; t++) {
        acc16[t] += __shfl_xor_sync(0xffffffffu, acc16[t], 16);
        acc16[t] += __shfl_xor_sync(0xffffffffu, acc16[t], 8);
        acc16[t] += __shfl_xor_sync(0xffffffffu, acc16[t], 4);
    }
    if (l < 4) {
        #pragma unroll
        for (int n = 0; n < 8; n++) {
            red[wid * 64 + n * 8 + l * 2]     = acc16[n * 2];
            red[wid * 64 + n * 8 + l * 2 + 1] = acc16[n * 2 + 1];
        }
    }
    __syncthreads();

    if (tid < 64) {
        float s = 0.f;
        #pragma unroll
        for (int w = 0; w < 8; w++) s += red[w * 64 + tid];
        xf[tid] = s;
    }
    __syncthreads();
    if (tid < 16) {
        float s = bf1[tid];
        for (int c = 0; c < 64; c++) s = fmaf(xf[c], Wf1[c * 16 + tid], s);
        hsm[tid] = fmaxf(s, 0.f);
    }
    __syncthreads();
    if (tid == 0) {
        float s = bf2[0];
        for (int t = 0; t < 16; t++) s = fmaf(hsm[t], Wf2[t], s);
        g_P[task] = 1.f / (1.f + expf(-s));
    }
}

// ---------------- final losses (cls mean + rn/sym) ----------------
__global__ void loss_kernel(const int* __restrict__ sy, const int* __restrict__ qy,
                            float* __restrict__ out) {
    __shared__ float es[256];
    __shared__ float s2[4], a2[4];
    int tid = threadIdx.x;
    if (tid < 4) { s2[tid] = 0.f; a2[tid] = 0.f; }
    __syncthreads();
    float e = 0.f;
    if (tid < NTASK) {
        int b = tid / 36, r = tid - b * 36;
        int J = r / 6, I = r - J * 6;
        float p  = g_P[tid];
        float pt = g_P[b * 36 + I * 6 + J];
        int labJ = (J < 5) ? sy[b * 5 + J] : qy[b];
        int labI = (I < 5) ? sy[b * 5 + I] : qy[b];
        float y = (labJ == labI) ? 1.f : 0.f;
        e = (p - y) * (p - y);
        float symv = 0.5f * (p + pt), antiv = 0.5f * (p - pt);
        atomicAdd(&s2[b], symv * symv);
        atomicAdd(&a2[b], antiv * antiv);
    }
    es[tid] = e;
    __syncthreads();
    for (int off = 128; off > 0; off >>= 1) {
        if (tid < off) es[tid] += es[tid + off];
        __syncthreads();
    }
    if (tid == 0) {
        float cls = 0.f;
        for (int n = 0; n < NIMG; n++) cls += g_lps[n];
        out[0] = -cls / (float)NIMG;
        float euc = es[0] / (float)NTASK;
        float sl = 0.f;
        for (int bb = 0; bb < 4; bb++) {
            float sn = sqrtf(s2[bb]), an = sqrtf(a2[bb]);
            sl += (sn - an) / (sn + an);
        }
        sl *= 0.25f;
        out[2] = sl;
        out[1] = euc - 0.1f * sl;
    }
}

// ---------------- launch ----------------
extern "C" void kernel_launch(void* const* d_in, const int* in_sizes, int n_in,
                              void* d_out, int out_size) {
    const float* sx   = (const float*)d_in[0];
    const int*   sy   = (const int*)  d_in[1];
    const float* qx   = (const float*)d_in[2];
    const int*   qy   = (const int*)  d_in[3];
    const float* k1   = (const float*)d_in[4];
    const float* bc1  = (const float*)d_in[5];
    const float* k2   = (const float*)d_in[6];
    const float* bc2  = (const float*)d_in[7];
    const float* k3   = (const float*)d_in[8];
    const float* bc3  = (const float*)d_in[9];
    const float* Wlog = (const float*)d_in[10];
    const float* blog = (const float*)d_in[11];
    const float* Wg1  = (const float*)d_in[12];
    const float* bg1  = (const float*)d_in[13];
    const float* Wg2  = (const float*)d_in[14];
    const float* bg2  = (const float*)d_in[15];
    const float* Wf1  = (const float*)d_in[16];
    const float* bf1  = (const float*)d_in[17];
    const float* Wf2  = (const float*)d_in[18];
    const float* bf2  = (const float*)d_in[19];
    float* out = (float*)d_out;

    const int smem_c1  = (((3  * 65 * 65 + 3) & ~3) + 8 * 27 ) * 4;
    const int smem_c2  = (((32 * 33 * 33 + 3) & ~3) + 8 * 288) * 4;
    const int smem_c3  = (((48 * 17 * 17 + 3) & ~3) + 8 * 432) * 4;
    const int smem_uv  = (64 * 68 + 2 * 66 * 64 + 64) * 4;
    const int smem_rel = (2 * 64 * PADK + 2 * 64 * PADW + 8 * 64 + 64 + 16) * 4;

    cudaFuncSetAttribute(conv1_k,       cudaFuncAttributeMaxDynamicSharedMemorySize, smem_c1);
    cudaFuncSetAttribute(conv2_k,       cudaFuncAttributeMaxDynamicSharedMemorySize, smem_c2);
    cudaFuncSetAttribute(conv3_k,       cudaFuncAttributeMaxDynamicSharedMemorySize, smem_c3);
    cudaFuncSetAttribute(uv_kernel,     cudaFuncAttributeMaxDynamicSharedMemorySize, smem_uv);
    cudaFuncSetAttribute(relnet_kernel, cudaFuncAttributeMaxDynamicSharedMemorySize, smem_rel);

    wprep_kernel<<<16, 256>>>(Wg2);
    conv1_k<<<dim3(NIMG, 4), 256, smem_c1>>>(sx, qx, k1, bc1);
    conv2_k<<<dim3(NIMG, 6), 256, smem_c2>>>(k2, bc2);
    conv3_k<<<dim3(NIMG, 8), 256, smem_c3>>>(k3, bc3);
    logits_kernel<<<NIMG, 64>>>(Wlog, blog, sy, qy);
    uv_kernel<<<dim3(NIMG, 2), 256, smem_uv>>>(Wg1, bg1);
    relnet_kernel<<<NTASK, 256, smem_rel>>>(bg2, Wf1, bf1, Wf2, bf2);
    loss_kernel<<<1, 256>>>(sy, qy, out);
}